// round 5
// baseline (speedup 1.0000x reference)
#include <cuda_runtime.h>

// ---------------------------------------------------------------------------
// ClustGeoNodeEncoder: per-cluster geometric features.
//   out[c] = [center(3), B(9)=cov/lambda_max, v0(3)=signed dir * dirwt, count]
//
// R4 change: k_accum packs TWO stats per 64-bit smem atomic (fixed point,
// scale 2^13, bias 512) -> 5 atomics/point instead of 10. k_accum was
// ATOMS-issue-bound (~1 lane-op/cyc/SM), so this halves the bottleneck.
//
// Pipeline:
//   k_accum : streaming pass, smem-privatized packed moments, partials->global
//   k_reduce: warp-per-cluster decode+reduce + 3x3 eigensolve (double)
//   k_sc    : streaming pass, sc = sum x0*||xc - x0 v0|| (smem float atomics)
//   k_final : finalize -> d_out (float4 stores)
// ---------------------------------------------------------------------------

#define MAXC 4096
#define NW   5            // packed u64 words per cluster
#define MAXB 192

#define FP_SCALE 8192.0f  // 2^13
#define FP_BIAS  512.0f
#define FP_ONE   8192ULL  // encoding of +1.0 (count, bias-free)

__device__ unsigned long long g_part[(size_t)MAXB * MAXC * NW];  // 31.5 MB
__device__ float4 g_cvec[MAXC * 2];   // [c*2]={cx,cy,cz,cnt} [c*2+1]={vx,vy,vz,0}
__device__ float  g_cov [MAXC * 6];   // a00,a11,a22,a01,a02,a12
__device__ float  g_w   [MAXC * 2];   // w1 (mid), w2 (max)
__device__ float  g_sc  [MAXC];

// ---------------------------------------------------------------------------

__device__ __forceinline__ unsigned long long encL(float v)
{
    return (unsigned long long)__float2uint_rn((v + FP_BIAS) * FP_SCALE);
}
__device__ __forceinline__ unsigned long long encP(float hi, float lo)
{
    unsigned int h = __float2uint_rn((hi + FP_BIAS) * FP_SCALE);
    unsigned int l = __float2uint_rn((lo + FP_BIAS) * FP_SCALE);
    return ((unsigned long long)h << 32) | (unsigned long long)l;
}

__device__ __forceinline__ void accum_point(unsigned long long* s, int id,
                                            float x, float y, float z)
{
    unsigned long long* b = s + id * NW;
    atomicAdd(b + 0, (FP_ONE << 32) | encL(x));          // count | x
    atomicAdd(b + 1, encP(y,     z));                    // y | z
    atomicAdd(b + 2, encP(x * x, y * y));                // xx | yy
    atomicAdd(b + 3, encP(z * z, x * y));                // zz | xy
    atomicAdd(b + 4, encP(x * z, y * z));                // xz | yz
}

__global__ __launch_bounds__(1024, 1)
void k_accum(const float* __restrict__ data, const int* __restrict__ ids, int n, int nc)
{
    extern __shared__ unsigned long long s[];
    const int tot = nc * NW;
    for (int j = threadIdx.x; j < tot; j += blockDim.x) s[j] = 0ULL;
    __syncthreads();

    const int gid    = blockIdx.x * blockDim.x + threadIdx.x;
    const int stride = gridDim.x * blockDim.x;
    const int nv4    = n >> 2;
    const float4* __restrict__ d4 = (const float4*)data;
    const int4*   __restrict__ i4 = (const int4*)ids;

    for (int g = gid; g < nv4; g += stride) {
        // 4 rows of 5 floats == 5 aligned float4 loads
        float4 q0 = d4[g * 5 + 0];
        float4 q1 = d4[g * 5 + 1];
        float4 q2 = d4[g * 5 + 2];
        float4 q3 = d4[g * 5 + 3];
        float4 q4 = d4[g * 5 + 4];
        int4   ii = i4[g];
        accum_point(s, ii.x, q0.x, q0.y, q0.z);
        accum_point(s, ii.y, q1.y, q1.z, q1.w);
        accum_point(s, ii.z, q2.z, q2.w, q3.x);
        accum_point(s, ii.w, q3.w, q4.x, q4.y);
    }
    for (int i = (nv4 << 2) + gid; i < n; i += stride) {
        accum_point(s, ids[i], data[i * 5 + 0], data[i * 5 + 1], data[i * 5 + 2]);
    }

    __syncthreads();
    unsigned long long* dst = g_part + (size_t)blockIdx.x * MAXC * NW;
    for (int j = threadIdx.x; j < tot; j += blockDim.x) dst[j] = s[j];
}

// ---------------------------------------------------------------------------
// 3x3 symmetric eigensolve (double): mid/max eigenvalues + unit eigenvector
// of the max eigenvalue (sign fixed later via sc, as in the reference).
// ---------------------------------------------------------------------------
__device__ void eig3_top(double a00, double a01, double a02,
                         double a11, double a12, double a22,
                         double& w1, double& w2,
                         double& vx, double& vy, double& vz)
{
    double q  = (a00 + a11 + a22) * (1.0 / 3.0);
    double p1 = a01 * a01 + a02 * a02 + a12 * a12;
    double b00 = a00 - q, b11 = a11 - q, b22 = a22 - q;
    double p2 = b00 * b00 + b11 * b11 + b22 * b22 + 2.0 * p1;
    if (p2 <= 1e-30) { w1 = q; w2 = q; vx = 0.0; vy = 0.0; vz = 1.0; return; }
    double p   = sqrt(p2 * (1.0 / 6.0));
    double inv = 1.0 / p;
    double c00 = b00 * inv, c11 = b11 * inv, c22 = b22 * inv;
    double c01 = a01 * inv, c02 = a02 * inv, c12 = a12 * inv;
    double detB = c00 * (c11 * c22 - c12 * c12)
                - c01 * (c01 * c22 - c12 * c02)
                + c02 * (c01 * c12 - c11 * c02);
    double r = fmin(1.0, fmax(-1.0, 0.5 * detB));
    double phi = acos(r) * (1.0 / 3.0);
    double e2 = q + 2.0 * p * cos(phi);                        // largest
    double e0 = q + 2.0 * p * cos(phi + 2.0943951023931953);   // smallest
    double e1 = 3.0 * q - e0 - e2;                             // middle
    w1 = e1; w2 = e2;

    double r0x = a00 - e2, r0y = a01,      r0z = a02;
    double r1x = a01,      r1y = a11 - e2, r1z = a12;
    double r2x = a02,      r2y = a12,      r2z = a22 - e2;

    double u0x = r0y * r1z - r0z * r1y, u0y = r0z * r1x - r0x * r1z, u0z = r0x * r1y - r0y * r1x;
    double u1x = r0y * r2z - r0z * r2y, u1y = r0z * r2x - r0x * r2z, u1z = r0x * r2y - r0y * r2x;
    double u2x = r1y * r2z - r1z * r2y, u2y = r1z * r2x - r1x * r2z, u2z = r1x * r2y - r1y * r2x;

    double n0 = u0x * u0x + u0y * u0y + u0z * u0z;
    double n1 = u1x * u1x + u1y * u1y + u1z * u1z;
    double n2 = u2x * u2x + u2y * u2y + u2z * u2z;

    double bx = u0x, by = u0y, bz = u0z, bn = n0;
    if (n1 > bn) { bx = u1x; by = u1y; bz = u1z; bn = n1; }
    if (n2 > bn) { bx = u2x; by = u2y; bz = u2z; bn = n2; }

    if (bn < 1e-200) { vx = 0.0; vy = 0.0; vz = 1.0; return; }
    double s = rsqrt(bn);
    vx = bx * s; vy = by * s; vz = bz * s;
}

__global__ void k_reduce(int nc, int nb)
{
    int w    = (blockIdx.x * blockDim.x + threadIdx.x) >> 5;
    int lane = threadIdx.x & 31;
    if (w >= nc) return;

    double hiS[NW], loS[NW];
#pragma unroll
    for (int k = 0; k < NW; k++) { hiS[k] = 0.0; loS[k] = 0.0; }

    for (int b = lane; b < nb; b += 32) {
        const unsigned long long* p = g_part + (size_t)b * MAXC * NW + w * NW;
#pragma unroll
        for (int k = 0; k < NW; k++) {
            unsigned long long v = p[k];
            hiS[k] += (double)(unsigned int)(v >> 32);
            loS[k] += (double)(unsigned int)(v & 0xffffffffULL);
        }
    }
#pragma unroll
    for (int off = 16; off; off >>= 1) {
#pragma unroll
        for (int k = 0; k < NW; k++) {
            hiS[k] += __shfl_down_sync(0xffffffffu, hiS[k], off);
            loS[k] += __shfl_down_sync(0xffffffffu, loS[k], off);
        }
    }
    if (lane != 0) return;

    const double S = 1.0 / (double)FP_SCALE;
    const double B = (double)FP_BIAS;
    double cnt = hiS[0] * S;                 // exact (bias-free)
    double bc  = B * cnt;
    double sx  = loS[0] * S - bc;
    double sy  = hiS[1] * S - bc;
    double sz  = loS[1] * S - bc;
    double sxx = hiS[2] * S - bc;
    double syy = loS[2] * S - bc;
    double szz = hiS[3] * S - bc;
    double sxy = loS[3] * S - bc;
    double sxz = hiS[4] * S - bc;
    double syz = loS[4] * S - bc;

    double safe = cnt > 1.0 ? cnt : 1.0;
    double cx = sx / safe, cy = sy / safe, cz = sz / safe;
    double a00 = sxx - cnt * cx * cx;
    double a11 = syy - cnt * cy * cy;
    double a22 = szz - cnt * cz * cz;
    double a01 = sxy - cnt * cx * cy;
    double a02 = sxz - cnt * cx * cz;
    double a12 = syz - cnt * cy * cz;

    double w1, w2, vx, vy, vz;
    eig3_top(a00, a01, a02, a11, a12, a22, w1, w2, vx, vy, vz);

    g_cvec[w * 2 + 0] = make_float4((float)cx, (float)cy, (float)cz, (float)cnt);
    g_cvec[w * 2 + 1] = make_float4((float)vx, (float)vy, (float)vz, 0.0f);
    g_cov[w * 6 + 0] = (float)a00;
    g_cov[w * 6 + 1] = (float)a11;
    g_cov[w * 6 + 2] = (float)a22;
    g_cov[w * 6 + 3] = (float)a01;
    g_cov[w * 6 + 4] = (float)a02;
    g_cov[w * 6 + 5] = (float)a12;
    g_w[w * 2 + 0] = (float)w1;
    g_w[w * 2 + 1] = (float)w2;
    g_sc[w] = 0.0f;   // reset before k_sc each replay
}

// ---------------------------------------------------------------------------

__device__ __forceinline__ void sc_point(float* s, int id, float x, float y, float z)
{
    float4 c  = g_cvec[id * 2 + 0];
    float4 v  = g_cvec[id * 2 + 1];
    float xcx = x - c.x, xcy = y - c.y, xcz = z - c.z;
    float x0  = xcx * v.x + xcy * v.y + xcz * v.z;
    float nn  = xcx * xcx + xcy * xcy + xcz * xcz - x0 * x0;
    float np0 = sqrtf(fmaxf(nn, 0.0f));
    atomicAdd(s + id, x0 * np0);
}

__global__ __launch_bounds__(1024, 1)
void k_sc(const float* __restrict__ data, const int* __restrict__ ids, int n, int nc)
{
    extern __shared__ float sf[];
    for (int j = threadIdx.x; j < nc; j += blockDim.x) sf[j] = 0.0f;
    __syncthreads();

    const int gid    = blockIdx.x * blockDim.x + threadIdx.x;
    const int stride = gridDim.x * blockDim.x;
    const int nv4    = n >> 2;
    const float4* __restrict__ d4 = (const float4*)data;
    const int4*   __restrict__ i4 = (const int4*)ids;

    for (int g = gid; g < nv4; g += stride) {
        float4 q0 = d4[g * 5 + 0];
        float4 q1 = d4[g * 5 + 1];
        float4 q2 = d4[g * 5 + 2];
        float4 q3 = d4[g * 5 + 3];
        float4 q4 = d4[g * 5 + 4];
        int4   ii = i4[g];
        sc_point(sf, ii.x, q0.x, q0.y, q0.z);
        sc_point(sf, ii.y, q1.y, q1.z, q1.w);
        sc_point(sf, ii.z, q2.z, q2.w, q3.x);
        sc_point(sf, ii.w, q3.w, q4.x, q4.y);
    }
    for (int i = (nv4 << 2) + gid; i < n; i += stride) {
        sc_point(sf, ids[i], data[i * 5 + 0], data[i * 5 + 1], data[i * 5 + 2]);
    }

    __syncthreads();
    for (int j = threadIdx.x; j < nc; j += blockDim.x) {
        float v = sf[j];
        if (v != 0.0f) atomicAdd(&g_sc[j], v);
    }
}

// ---------------------------------------------------------------------------

__global__ void k_final(float* __restrict__ out, int nc)
{
    int c = blockIdx.x * blockDim.x + threadIdx.x;
    if (c >= nc) return;

    float4 cc = g_cvec[c * 2 + 0];
    float4 vv = g_cvec[c * 2 + 1];
    float  cnt = cc.w;
    float  w1 = g_w[c * 2 + 0];
    float  w2 = g_w[c * 2 + 1];
    float  sc = g_sc[c];

    bool  small = cnt < 2.0f;
    float dirwt = (w2 == 0.0f) ? 0.0f : (1.0f - w1 / w2);
    float denom = (w2 == 0.0f) ? 1.0f : w2;
    float bs    = small ? 0.0f : (1.0f / denom);        // B = cov / lambda_max
    float vscl  = small ? 0.0f : ((sc < 0.0f) ? -dirwt : dirwt);

    float a00 = g_cov[c * 6 + 0] * bs;
    float a11 = g_cov[c * 6 + 1] * bs;
    float a22 = g_cov[c * 6 + 2] * bs;
    float a01 = g_cov[c * 6 + 3] * bs;
    float a02 = g_cov[c * 6 + 4] * bs;
    float a12 = g_cov[c * 6 + 5] * bs;

    float4* o4 = (float4*)(out + (size_t)c * 16);
    o4[0] = make_float4(cc.x, cc.y, cc.z, a00);
    o4[1] = make_float4(a01, a02, a01, a11);
    o4[2] = make_float4(a12, a02, a12, a22);
    o4[3] = make_float4(vv.x * vscl, vv.y * vscl, vv.z * vscl, cnt);
}

// ---------------------------------------------------------------------------

extern "C" void kernel_launch(void* const* d_in, const int* in_sizes, int n_in,
                              void* d_out, int out_size)
{
    const float* data = (const float*)d_in[0];
    const int*   ids  = (const int*)d_in[1];
    const int    n    = in_sizes[1];
    int nc = out_size / 16;
    if (nc > MAXC) nc = MAXC;
    float* out = (float*)d_out;

    int sm = 148;
    cudaDeviceGetAttribute(&sm, cudaDevAttrMultiProcessorCount, 0);
    int nb = sm;
    if (nb > MAXB) nb = MAXB;
    if (nb < 1)    nb = 1;

    const size_t smem1 = (size_t)nc * NW * sizeof(unsigned long long);  // 163,840 B
    cudaFuncSetAttribute(k_accum, cudaFuncAttributeMaxDynamicSharedMemorySize, (int)smem1);
    cudaFuncSetAttribute(k_sc,    cudaFuncAttributeMaxDynamicSharedMemorySize,
                         (int)((size_t)nc * sizeof(float)));

    k_accum<<<nb, 1024, smem1>>>(data, ids, n, nc);
    k_reduce<<<(nc * 32 + 255) / 256, 256>>>(nc, nb);
    k_sc<<<nb, 1024, (size_t)nc * sizeof(float)>>>(data, ids, n, nc);
    k_final<<<(nc + 255) / 256, 256>>>(out, nc);
}